// round 10
// baseline (speedup 1.0000x reference)
#include <cuda_runtime.h>

// HOG layer, fully register-resident: Sobel -> mag + comparison-based 9-bin
// orientation hist -> 8x8 mean pool. No shared memory, no atomics, no syncs.
// Input : x (64,1,512,512) fp32. Output: (64, 9*64*64) fp32.
//
// Thread = 4 cols x 8 rows patch (inside ONE 8x8 cell). Block = 128 threads
// = 16 col-groups (64 cols) x 8 row-groups (64 rows). Lane l and l^1 cover
// the two column-halves of the same cell -> cell reduce = one shfl.xor(1).
//
// Bin math: bin = floor(9*atan2(gx,gy)/pi) mod 9 depends only on
// cot(theta) = gy/gx; monotone predicates p_k = [rat <= cot(k*pi/9)] give
// cumulative sums C_k; bins recovered via bin_b = C_{b-1} - C_{b+1}
// (bin0 = C0 - C1 + C8, bin8 = C7).
//
// R10 = R8 + packed f32x2 arithmetic (sm_103a add/mul/fma.rn.f32x2 via inline
// PTX) for the row filter, gradient combine and r^2 -- one issue slot per two
// f32 lanes. MUFU sqrt/rcp and FSETP binning stay scalar on the pair halves.
// Rounding of fma/add.f32x2 == scalar, so results are bit-identical to R8.

#define ORI 9

typedef unsigned long long u64;

// packed {lo,hi} f32 pair helpers (sm_100+ f32x2 ALU ops; ptxas won't auto-fuse)
__device__ __forceinline__ u64 pk2(float lo, float hi) {
    u64 r; asm("mov.b64 %0, {%1, %2};" : "=l"(r) : "f"(lo), "f"(hi)); return r;
}
__device__ __forceinline__ void upk2(u64 p, float& lo, float& hi) {
    asm("mov.b64 {%0, %1}, %2;" : "=f"(lo), "=f"(hi) : "l"(p));
}
__device__ __forceinline__ u64 add2(u64 a, u64 b) {
    u64 r; asm("add.rn.f32x2 %0, %1, %2;" : "=l"(r) : "l"(a), "l"(b)); return r;
}
__device__ __forceinline__ u64 mul2(u64 a, u64 b) {
    u64 r; asm("mul.rn.f32x2 %0, %1, %2;" : "=l"(r) : "l"(a), "l"(b)); return r;
}
__device__ __forceinline__ u64 fma2(u64 a, u64 b, u64 c) {
    u64 r; asm("fma.rn.f32x2 %0, %1, %2, %3;" : "=l"(r) : "l"(a), "l"(b), "l"(c)); return r;
}

#define F2_TWO  0x4000000040000000ULL   /* { 2.0f,  2.0f} */
#define F2_NEG1 0xBF800000BF800000ULL   /* {-1.0f, -1.0f} */

__device__ __forceinline__ float fsqrt_approx(float v) {
    float y;
    asm("sqrt.approx.f32 %0, %1;" : "=f"(y) : "f"(v));
    return y;
}

// Packed row-filter values for 4 columns: t_i = left-right, h_i = left+2*mid+right.
struct RowTH { u64 t01, t23, h01, h23; };

__device__ __forceinline__ RowTH row_filter(float lf, float4 v, float rt) {
    u64 l01 = pk2(lf,  v.x);
    u64 yz  = pk2(v.y, v.z);
    u64 r23 = pk2(v.w, rt);
    u64 xy  = pk2(v.x, v.y);
    u64 zw  = pk2(v.z, v.w);
    RowTH o;
    o.t01 = fma2(yz,  F2_NEG1, l01);            // {lf-y,  x-z}
    o.t23 = fma2(r23, F2_NEG1, yz);             // {y-w,   z-rt}
    o.h01 = add2(fma2(xy, F2_TWO, l01), yz);    // {lf+2x+y, x+2y+z}
    o.h23 = add2(fma2(zw, F2_TWO, yz),  r23);   // {y+2z+w,  z+2w+rt}
    return o;
}

// Unconditional row load (row known in-bounds).
__device__ __forceinline__ RowTH load_row(const float* __restrict__ rp,
                                          bool leftEdge, bool rightEdge) {
    float4 v = *reinterpret_cast<const float4*>(rp);
    float lf = leftEdge  ? 0.f : __ldg(rp - 1);
    float rt = rightEdge ? 0.f : __ldg(rp + 4);
    return row_filter(lf, v, rt);
}

// Row load that may be fully out of bounds (zero row). Used twice per thread.
__device__ __forceinline__ RowTH load_row_maybe(const float* __restrict__ rp,
                                                bool valid,
                                                bool leftEdge, bool rightEdge) {
    float4 v = make_float4(0.f, 0.f, 0.f, 0.f);
    float lf = 0.f, rt = 0.f;
    if (valid) {
        v = *reinterpret_cast<const float4*>(rp);
        if (!leftEdge)  lf = __ldg(rp - 1);
        if (!rightEdge) rt = __ldg(rp + 4);
    }
    return row_filter(lf, v, rt);
}

// Scalar binning for one pixel: accumulate cumulative sums C[0..8].
__device__ __forceinline__ void bin1(float gx, float gy, float r2, float* C) {
    // cot(k*pi/9), k = 1..8 (strictly decreasing)
    const float COT[8] = {
         2.7474774194546225f,
         1.1917535925942100f,
         0.5773502691896258f,
         0.1763269807084650f,
        -0.1763269807084650f,
        -0.5773502691896257f,
        -1.1917535925942100f,
        -2.7474774194546230f
    };
    float mag = fsqrt_approx(r2);          // sqrt.approx(0) == 0
    float rat = __fdividef(gy, gx);        // cot(theta); +-inf at gx==0

    C[0] += mag;
    #pragma unroll
    for (int k = 0; k < 8; k++)
        if (rat <= COT[k]) C[k + 1] += mag;
}

// 4-pixel core: packed gradient + r^2, scalar mag/rat/binning.
__device__ __forceinline__ void bin4(const RowTH& a, const RowTH& b,
                                     const RowTH& c, float* C) {
    u64 gx01 = add2(fma2(b.t01, F2_TWO, a.t01), c.t01);
    u64 gx23 = add2(fma2(b.t23, F2_TWO, a.t23), c.t23);
    u64 gy01 = fma2(c.h01, F2_NEG1, a.h01);
    u64 gy23 = fma2(c.h23, F2_NEG1, a.h23);
    u64 r201 = fma2(gx01, gx01, mul2(gy01, gy01));
    u64 r223 = fma2(gx23, gx23, mul2(gy23, gy23));

    float gx0, gx1, gx2, gx3, gy0, gy1, gy2, gy3, r20, r21, r22, r23v;
    upk2(gx01, gx0, gx1);  upk2(gx23, gx2, gx3);
    upk2(gy01, gy0, gy1);  upk2(gy23, gy2, gy3);
    upk2(r201, r20, r21);  upk2(r223, r22, r23v);

    bin1(gx0, gy0, r20,  C);
    bin1(gx1, gy1, r21,  C);
    bin1(gx2, gy2, r22,  C);
    bin1(gx3, gy3, r23v, C);
}

__global__ __launch_bounds__(128, 8) void hog_kernel(const float* __restrict__ x,
                                                     float* __restrict__ out)
{
    const int n    = blockIdx.z;
    const int row0 = blockIdx.y * 64;
    const int col0 = blockIdx.x * 64;
    const int tid  = threadIdx.x;
    const int cg   = tid & 15;        // col-group (4 cols each)
    const int rg   = tid >> 4;        // row-group (8 rows each)

    const int c0 = col0 + cg * 4;     // first output col of this thread
    const int r0 = row0 + rg * 8;     // first output row; r0 in [0, 504]

    const float* __restrict__ img = x + (size_t)n * (512 * 512);
    const float* __restrict__ rp0 = img + r0 * 512 + c0;

    const bool leftEdge  = (c0 == 0);
    const bool rightEdge = (c0 == 508);
    const bool topOK     = (r0 != 0);     // row r0-1 valid?
    const bool botOK     = (r0 != 504);   // row r0+8 valid?

    float C[9];
    #pragma unroll
    for (int b = 0; b < 9; b++) C[b] = 0.0f;

    RowTH a = load_row_maybe(rp0 - 512, topOK, leftEdge, rightEdge);
    RowTH b = load_row(rp0, leftEdge, rightEdge);

    #pragma unroll
    for (int s = 0; s < 7; s++) {
        RowTH c = load_row(rp0 + (s + 1) * 512, leftEdge, rightEdge);
        bin4(a, b, c, C);
        a = b; b = c;
    }
    {   // last step: row r0+8 may be out of bounds
        RowTH c = load_row_maybe(rp0 + 8 * 512, botOK, leftEdge, rightEdge);
        bin4(a, b, c, C);
    }

    // ---- cell reduction: partner lane (lane^1) holds the other 4 columns ----
    #pragma unroll
    for (int q = 0; q < 9; q++)
        C[q] += __shfl_xor_sync(0xffffffffu, C[q], 1);

    // ---- recover bins, write pooled output (split 9 bins across the pair) ----
    const int ch = (row0 >> 3) + rg;
    const int cw = (col0 >> 3) + (cg >> 1);
    float* obase = out + (size_t)n * (ORI * 64 * 64) + ch * 64 + cw;

    float bins[9];
    bins[0] = C[0] - C[1] + C[8];
    #pragma unroll
    for (int q = 1; q < 8; q++) bins[q] = C[q - 1] - C[q + 1];
    bins[8] = C[7];

    if ((cg & 1) == 0) {
        #pragma unroll
        for (int q = 0; q < 5; q++)
            obase[q * 4096] = bins[q] * (1.0f / 64.0f);
    } else {
        #pragma unroll
        for (int q = 5; q < 9; q++)
            obase[q * 4096] = bins[q] * (1.0f / 64.0f);
    }
}

extern "C" void kernel_launch(void* const* d_in, const int* in_sizes, int n_in,
                              void* d_out, int out_size)
{
    const float* x   = (const float*)d_in[0];
    float*       out = (float*)d_out;

    dim3 grid(512 / 64, 512 / 64, 64);
    hog_kernel<<<grid, 128>>>(x, out);
}